// round 7
// baseline (speedup 1.0000x reference)
#include <cuda_runtime.h>
#include <cstdint>
#include <cstddef>

// Reverse LSTM: B=128, T=2048, H=512.  out[b,t,:] = h_t (consumes x[b, T-1-t]).
//
// Persistent kernel: 128 CTAs = 4 batch-groups (bg, 32 rows) x 32 col-groups
// (cg, 16 h-cols = 64 z-cols). Wh slice (128KB) SMEM-resident.
// R6: zero-pack FFMA2 GEMM — pairs ride the k-dimension, so BOTH operands come
// pre-paired from LDS.128 (h stored [b][k]; Wh stored [kq][g][j][kk] for
// conflict-free 16B-stride lane access). Accumulators hold (even-k, odd-k)
// partial sums, folded once per step. TMA bulk staging in 2 pipelined halves.

#define TT   2048
#define HID  512
#define FPAD 32              // flag padding (uints) -> 128B per flag

__device__ float    g_Hbuf[2][4][32 * HID];    // [parity][bg][b*512 + k]  b-major
__device__ unsigned g_flag[4][32][FPAD];       // [bg][cg][0], padded

typedef unsigned long long u64;

__device__ __forceinline__ void ffma2(u64 &d, u64 a, u64 b) {
    asm volatile("fma.rn.f32x2 %0, %1, %2, %0;" : "+l"(d) : "l"(a), "l"(b));
}
__device__ __forceinline__ float lo32(u64 v) { return __uint_as_float((unsigned)v); }
__device__ __forceinline__ float hi32(u64 v) { return __uint_as_float((unsigned)(v >> 32)); }
__device__ __forceinline__ float fold(u64 v) { return lo32(v) + hi32(v); }

__device__ __forceinline__ void poll_flag(const unsigned* f, unsigned tgt) {
    unsigned v;
    do {
        asm volatile("ld.acquire.gpu.global.u32 %0, [%1];" : "=r"(v) : "l"(f));
    } while (v < tgt);
}
__device__ __forceinline__ void bulk_g2s(unsigned dst_smem, const void* src,
                                         unsigned bytes, unsigned mbar) {
    asm volatile(
        "cp.async.bulk.shared::cluster.global.mbarrier::complete_tx::bytes "
        "[%0], [%1], %2, [%3];"
        :: "r"(dst_smem), "l"(src), "r"(bytes), "r"(mbar) : "memory");
}
__device__ __forceinline__ void mbar_init(unsigned mbar, unsigned cnt) {
    asm volatile("mbarrier.init.shared.b64 [%0], %1;" :: "r"(mbar), "r"(cnt) : "memory");
}
__device__ __forceinline__ void mbar_expect_tx(unsigned mbar, unsigned bytes) {
    asm volatile("mbarrier.arrive.expect_tx.shared.b64 _, [%0], %1;"
                 :: "r"(mbar), "r"(bytes) : "memory");
}
__device__ __forceinline__ void mbar_wait(unsigned mbar, unsigned parity) {
    unsigned done;
    asm volatile(
        "{\n\t.reg .pred p;\n\t"
        "mbarrier.try_wait.parity.acquire.cta.shared::cta.b64 p, [%1], %2;\n\t"
        "selp.b32 %0, 1, 0, p;\n\t}"
        : "=r"(done) : "r"(mbar), "r"(parity) : "memory");
    if (!done) {
        asm volatile(
            "{\n\t.reg .pred P1;\n\t"
            "WL_%=:\n\t"
            "mbarrier.try_wait.parity.acquire.cta.shared::cta.b64 P1, [%0], %1, 0x989680;\n\t"
            "@P1 bra.uni WD_%=;\n\t"
            "bra.uni WL_%=;\n\t"
            "WD_%=:\n\t}"
            :: "r"(mbar), "r"(parity) : "memory");
    }
}

__global__ void lstm_init_kernel() {
    int i = threadIdx.x;                // 128 = 4*32 flags
    g_flag[i >> 5][i & 31][0] = 0u;
}

extern __shared__ float sm[];

__global__ void __launch_bounds__(128, 1)
lstm_persistent_kernel(const float* __restrict__ x,
                       const float* __restrict__ Wi,
                       const float* __restrict__ Wh,
                       const float* __restrict__ bias,
                       float* __restrict__ out)
{
    // SMEM (floats):
    //  Wh_s [kq=128][g=4][j=16][kk=4] = 32768 fl (128KB) @ 0
    //  h_s  [b=32][k=512]             = 16384 fl ( 64KB) @ 32768
    //  x_s  [32]                                 @ 49152
    //  mbar u64 x2                               @ 49184 (16B aligned)
    float* Wh_s = sm;
    float* h_s  = sm + 32768;
    float* x_s  = sm + 49152;

    const int tid = threadIdx.x;
    const int bg  = blockIdx.x >> 5;     // 0..3
    const int cg  = blockIdx.x & 31;     // 0..31 -> h-cols cg*16..cg*16+15
    const int j   = tid & 15;            // local h-col
    const int bq  = tid >> 4;            // batch quad (0..7)

    const unsigned smem_base = (unsigned)__cvta_generic_to_shared(sm);
    const unsigned h_smem    = smem_base + 32768u * 4u;
    const unsigned mbar0     = smem_base + 49184u * 4u;
    const unsigned mbar1     = mbar0 + 8u;

    if (tid == 0) { mbar_init(mbar0, 1); mbar_init(mbar1, 1); }

    // ---- One-time: Wh slice into [kq][g][j][kk] layout ----
    for (int idx = tid; idx < 32768; idx += 128) {
        int kq = idx >> 8;
        int g  = (idx >> 6) & 3;
        int jj = (idx >> 2) & 15;
        int kk = idx & 3;
        int k  = kq * 4 + kk;
        Wh_s[idx] = Wh[(size_t)k * 2048 + g * 512 + cg * 16 + jj];
    }
    float wi_r[4], bi_r[4];
    #pragma unroll
    for (int g = 0; g < 4; ++g) {
        wi_r[g] = Wi[g * 512 + cg * 16 + j];
        bi_r[g] = bias[g * 512 + cg * 16 + j];
    }
    __syncthreads();

    float cst[4] = {0.f, 0.f, 0.f, 0.f};
    const size_t TH = (size_t)TT * HID;

    for (int t = 0; t < TT; ++t) {
        // x for this step (warp 1; consumed after the syncthreads below)
        if (tid >= 32 && tid < 64)
            x_s[tid - 32] = x[(size_t)(bg * 32 + (tid - 32)) * TT + (TT - 1 - t)];

        const unsigned ph = (unsigned)((t + 1) & 1);   // mbar parity for step t (t>=1)

        if (t > 0) {
            const float* Hsrc = &g_Hbuf[t & 1][bg][0];
            const unsigned tgt = (unsigned)t;
            // warp 0: lanes 0-15 gate half0 (k 0..255 <- producers cg 0..15),
            //         lanes 16-31 gate half1 (k 256..511 <- producers cg 16..31).
            // New h layout is b-major, so each half is 32 strided 1KB rows.
            if (tid < 16) {
                poll_flag(&g_flag[bg][tid][0], tgt);
                __syncwarp(0x0000FFFFu);
                if (tid == 0) {
                    mbar_expect_tx(mbar0, 32768u);
                    #pragma unroll 8
                    for (int b = 0; b < 32; ++b)
                        bulk_g2s(h_smem + b * 2048u, Hsrc + b * 512, 1024u, mbar0);
                }
            } else if (tid < 32) {
                poll_flag(&g_flag[bg][tid][0], tgt);
                __syncwarp(0xFFFF0000u);
                if (tid == 16) {
                    mbar_expect_tx(mbar1, 32768u);
                    #pragma unroll 8
                    for (int b = 0; b < 32; ++b)
                        bulk_g2s(h_smem + b * 2048u + 1024u, Hsrc + b * 512 + 256, 1024u, mbar1);
                }
            }
            mbar_wait(mbar0, ph);
        }
        __syncthreads();   // x_s visible (and uniform control at t=0)

        // accumulators: a[r][g], each u64 = (sum over even k, sum over odd k)
        u64 a00=0,a01=0,a02=0,a03=0, a10=0,a11=0,a12=0,a13=0;
        u64 a20=0,a21=0,a22=0,a23=0, a30=0,a31=0,a32=0,a33=0;

        if (t > 0) {
            // ---- GEMM half Q (256 k = 64 quads): zero packs ----
            #define GEMM_HALF(Q) do {                                              \
                const float* hp = h_s  + (bq * 4) * 512 + (Q) * 256;               \
                const float* wp = Wh_s + (Q) * 16384 + j * 4;                      \
                _Pragma("unroll 4")                                                \
                for (int kq = 0; kq < 64; ++kq) {                                  \
                    ulonglong2 h0 = *(const ulonglong2*)(hp + kq * 4);             \
                    ulonglong2 h1 = *(const ulonglong2*)(hp + 512  + kq * 4);      \
                    ulonglong2 h2 = *(const ulonglong2*)(hp + 1024 + kq * 4);      \
                    ulonglong2 h3 = *(const ulonglong2*)(hp + 1536 + kq * 4);      \
                    ulonglong2 w0 = *(const ulonglong2*)(wp + kq * 256);           \
                    ulonglong2 w1 = *(const ulonglong2*)(wp + kq * 256 + 64);      \
                    ulonglong2 w2 = *(const ulonglong2*)(wp + kq * 256 + 128);     \
                    ulonglong2 w3 = *(const ulonglong2*)(wp + kq * 256 + 192);     \
                    ffma2(a00, h0.x, w0.x); ffma2(a00, h0.y, w0.y);                \
                    ffma2(a01, h0.x, w1.x); ffma2(a01, h0.y, w1.y);                \
                    ffma2(a02, h0.x, w2.x); ffma2(a02, h0.y, w2.y);                \
                    ffma2(a03, h0.x, w3.x); ffma2(a03, h0.y, w3.y);                \
                    ffma2(a10, h1.x, w0.x); ffma2(a10, h1.y, w0.y);                \
                    ffma2(a11, h1.x, w1.x); ffma2(a11, h1.y, w1.y);                \
                    ffma2(a12, h1.x, w2.x); ffma2(a12, h1.y, w2.y);                \
                    ffma2(a13, h1.x, w3.x); ffma2(a13, h1.y, w3.y);                \
                    ffma2(a20, h2.x, w0.x); ffma2(a20, h2.y, w0.y);                \
                    ffma2(a21, h2.x, w1.x); ffma2(a21, h2.y, w1.y);                \
                    ffma2(a22, h2.x, w2.x); ffma2(a22, h2.y, w2.y);                \
                    ffma2(a23, h2.x, w3.x); ffma2(a23, h2.y, w3.y);                \
                    ffma2(a30, h3.x, w0.x); ffma2(a30, h3.y, w0.y);                \
                    ffma2(a31, h3.x, w1.x); ffma2(a31, h3.y, w1.y);                \
                    ffma2(a32, h3.x, w2.x); ffma2(a32, h3.y, w2.y);                \
                    ffma2(a33, h3.x, w3.x); ffma2(a33, h3.y, w3.y);                \
                }                                                                  \
            } while (0)

            GEMM_HALF(0);
            mbar_wait(mbar1, ph);
            GEMM_HALF(1);
            #undef GEMM_HALF
        }

        // ---- gates (fold even/odd partials), state update, publish ----
        {
            float zi_[4] = { fold(a00), fold(a10), fold(a20), fold(a30) };
            float zf_[4] = { fold(a01), fold(a11), fold(a21), fold(a31) };
            float zg_[4] = { fold(a02), fold(a12), fold(a22), fold(a32) };
            float zo_[4] = { fold(a03), fold(a13), fold(a23), fold(a33) };
            float4 xv = *(const float4*)(x_s + bq * 4);
            float xv_[4] = { xv.x, xv.y, xv.z, xv.w };

            size_t obase = (size_t)(bg * 32 + bq * 4) * TH
                         + (size_t)t * HID + cg * 16 + j;
            float* hnb = &g_Hbuf[(t + 1) & 1][bg][0];
            #pragma unroll
            for (int r = 0; r < 4; ++r) {
                float xr = xv_[r];
                float vi = zi_[r] + xr * wi_r[0] + bi_r[0];
                float vf = zf_[r] + xr * wi_r[1] + bi_r[1];
                float vg = zg_[r] + xr * wi_r[2] + bi_r[2];
                float vo = zo_[r] + xr * wi_r[3] + bi_r[3];
                float ig = 1.0f / (1.0f + __expf(-vi));
                float fg = 1.0f / (1.0f + __expf(-vf));
                float eg = __expf(2.0f * vg);
                float gv = 1.0f - 2.0f / (eg + 1.0f);         // tanh(vg)
                float og = 1.0f / (1.0f + __expf(-vo));
                float cn = fg * cst[r] + ig * gv;
                cst[r] = cn;
                float ec = __expf(2.0f * cn);
                float hr = og * (1.0f - 2.0f / (ec + 1.0f));  // o * tanh(c)
                out[obase + (size_t)r * TH] = hr;
                // b-major publish: Hbuf[b][k]
                hnb[(bq * 4 + r) * 512 + cg * 16 + j] = hr;
            }
        }

        // ---- release: all h published -> fence -> bump this CTA's flag ----
        __syncthreads();
        if (tid == 0) {
            __threadfence();
            asm volatile("st.release.gpu.global.u32 [%0], %1;"
                         :: "l"(&g_flag[bg][cg][0]), "r"((unsigned)(t + 1))
                         : "memory");
        }
    }
}

extern "C" void kernel_launch(void* const* d_in, const int* in_sizes, int n_in,
                              void* d_out, int out_size)
{
    // inputs: [0]=s (unused), [1]=x (128*2048), [2]=Wi (2048), [3]=Wh (512*2048), [4]=b (2048)
    const float* x    = (const float*)d_in[1];
    const float* Wi   = (const float*)d_in[2];
    const float* Wh   = (const float*)d_in[3];
    const float* bias = (const float*)d_in[4];
    float* out = (float*)d_out;

    size_t smem = (size_t)(49184 + 8) * sizeof(float);   // 196768 B
    cudaFuncSetAttribute(lstm_persistent_kernel,
                         cudaFuncAttributeMaxDynamicSharedMemorySize, (int)smem);

    lstm_init_kernel<<<1, 128>>>();
    lstm_persistent_kernel<<<128, 128, smem>>>(x, Wi, Wh, bias, out);
}

// round 8
// speedup vs baseline: 1.1609x; 1.1609x over previous
#include <cuda_runtime.h>
#include <cstdint>
#include <cstddef>

// Reverse LSTM: B=128, T=2048, H=512.  out[b,t,:] = h_t (consumes x[b, T-1-t]).
//
// Persistent kernel: 128 CTAs = 4 batch-groups (bg, 32 rows) x 32 col-groups
// (cg, 16 h-cols = 64 z-cols). Wh slice (128KB) SMEM-resident.
// R7: 256 threads/CTA = 2 warps per SMSP (R2-R6 all ran 1 warp/SMSP and were
// stall-bound at issue=25-33%). GEMM k-split: warps 0-3 do k<256, warps 4-7
// k>=256, same R2 inner loop (15 issues/k, FMA-bound); partial z reduced via
// one SMEM exchange. TMA bulk staging in 2 halves, each gated by its own mbar
// so each half-CTA starts as soon as its k-range is resident.

#define TT   2048
#define HID  512
#define FPAD 32              // flag padding (uints) -> 128B per flag
#define ZPAD 34              // z exchange row pad (floats)

__device__ float    g_Hbuf[2][4][HID * 32];    // [parity][bg][k*32 + b]  k-major
__device__ unsigned g_flag[4][32][FPAD];       // [bg][cg][0], padded

typedef unsigned long long u64;

__device__ __forceinline__ void ffma2(u64 &d, u64 a, u64 b) {
    asm volatile("fma.rn.f32x2 %0, %1, %2, %0;" : "+l"(d) : "l"(a), "l"(b));
}
__device__ __forceinline__ u64 pack2(float x) {
    u64 r; asm("mov.b64 %0, {%1, %1};" : "=l"(r) : "f"(x)); return r;
}
__device__ __forceinline__ float lo32(u64 v) { return __uint_as_float((unsigned)v); }
__device__ __forceinline__ float hi32(u64 v) { return __uint_as_float((unsigned)(v >> 32)); }

__device__ __forceinline__ void poll_flag(const unsigned* f, unsigned tgt) {
    unsigned v;
    do {
        asm volatile("ld.acquire.gpu.global.u32 %0, [%1];" : "=r"(v) : "l"(f));
    } while (v < tgt);
}
__device__ __forceinline__ void bulk_g2s(unsigned dst_smem, const void* src,
                                         unsigned bytes, unsigned mbar) {
    asm volatile(
        "cp.async.bulk.shared::cluster.global.mbarrier::complete_tx::bytes "
        "[%0], [%1], %2, [%3];"
        :: "r"(dst_smem), "l"(src), "r"(bytes), "r"(mbar) : "memory");
}
__device__ __forceinline__ void mbar_init(unsigned mbar, unsigned cnt) {
    asm volatile("mbarrier.init.shared.b64 [%0], %1;" :: "r"(mbar), "r"(cnt) : "memory");
}
__device__ __forceinline__ void mbar_expect_tx(unsigned mbar, unsigned bytes) {
    asm volatile("mbarrier.arrive.expect_tx.shared.b64 _, [%0], %1;"
                 :: "r"(mbar), "r"(bytes) : "memory");
}
__device__ __forceinline__ void mbar_wait(unsigned mbar, unsigned parity) {
    unsigned done;
    asm volatile(
        "{\n\t.reg .pred p;\n\t"
        "mbarrier.try_wait.parity.acquire.cta.shared::cta.b64 p, [%1], %2;\n\t"
        "selp.b32 %0, 1, 0, p;\n\t}"
        : "=r"(done) : "r"(mbar), "r"(parity) : "memory");
    if (!done) {
        asm volatile(
            "{\n\t.reg .pred P1;\n\t"
            "WL_%=:\n\t"
            "mbarrier.try_wait.parity.acquire.cta.shared::cta.b64 P1, [%0], %1, 0x989680;\n\t"
            "@P1 bra.uni WD_%=;\n\t"
            "bra.uni WL_%=;\n\t"
            "WD_%=:\n\t}"
            :: "r"(mbar), "r"(parity) : "memory");
    }
}

__global__ void lstm_init_kernel() {
    int i = threadIdx.x;                // 128 = 4*32 flags
    g_flag[i >> 5][i & 31][0] = 0u;
}

extern __shared__ float sm[];

__global__ void __launch_bounds__(256, 1)
lstm_persistent_kernel(const float* __restrict__ x,
                       const float* __restrict__ Wi,
                       const float* __restrict__ Wh,
                       const float* __restrict__ bias,
                       float* __restrict__ out)
{
    // SMEM (floats):
    //  Wh_s [k=512][c=64]          @ 0       (131072 B)   c = g*16 + j
    //  h_s  [k=512][b=32]          @ 32768   ( 65536 B)   k-major
    //  z2   [kh=2][c=64][ZPAD]     @ 49152   ( 17408 B)
    //  x_s  [32]                   @ 53504
    //  mbar u64 x2                 @ 53536   (16B aligned)
    float* Wh_s = sm;
    float* h_s  = sm + 32768;
    float* z2   = sm + 49152;
    float* x_s  = sm + 53504;

    const int tid = threadIdx.x;
    const int bg  = blockIdx.x >> 5;     // 0..3
    const int cg  = blockIdx.x & 31;     // 0..31 -> h-cols cg*16..cg*16+15

    const int kh   = tid >> 7;           // k-half: warps 0-3 -> 0, 4-7 -> 1
    const int id   = tid & 127;
    const int lane = id & 31;            // col-pair (cols 2*lane, 2*lane+1)
    const int oct  = id >> 5;            // batch octet (b = oct*8 .. oct*8+7)

    const int j  = tid & 15;             // gate-phase h-col
    const int bh = tid >> 4;             // gate-phase batch pair (b0 = 2*bh)
    const int b0 = bh * 2;

    const unsigned smem_base = (unsigned)__cvta_generic_to_shared(sm);
    const unsigned h_smem    = smem_base + 32768u * 4u;
    const unsigned mbar0     = smem_base + 53536u * 4u;
    const unsigned mbar1     = mbar0 + 8u;

    if (tid == 0) { mbar_init(mbar0, 1); mbar_init(mbar1, 1); }

    // ---- One-time: Wh slice (col c = g*16+j <-> global g*512 + cg*16 + j) ----
    for (int idx = tid; idx < HID * 64; idx += 256) {
        int k = idx >> 6, c = idx & 63;
        Wh_s[idx] = Wh[(size_t)k * 2048 + (c >> 4) * 512 + cg * 16 + (c & 15)];
    }
    float wi_r[4], bi_r[4];
    #pragma unroll
    for (int g = 0; g < 4; ++g) {
        wi_r[g] = Wi[g * 512 + cg * 16 + j];
        bi_r[g] = bias[g * 512 + cg * 16 + j];
    }
    __syncthreads();

    float c0s = 0.f, c1s = 0.f;          // cell state for (b0, b0+1)
    const size_t TH = (size_t)TT * HID;

    const float* hp = h_s  + kh * 8192  + oct * 8;
    const float* wp = Wh_s + kh * 16384 + lane * 2;
    const unsigned my_mbar = kh ? mbar1 : mbar0;

    for (int t = 0; t < TT; ++t) {
        // x for this step (warp 1; consumed after the z2 syncthreads)
        if (tid >= 32 && tid < 64)
            x_s[tid - 32] = x[(size_t)(bg * 32 + (tid - 32)) * TT + (TT - 1 - t)];

        const unsigned ph = (unsigned)((t + 1) & 1);

        if (t > 0) {
            const float* Hsrc = &g_Hbuf[t & 1][bg][0];
            const unsigned tgt = (unsigned)t;
            // warp 0: lanes 0-15 gate half0 (k<256 <- producers cg 0..15),
            //         lanes 16-31 gate half1 (k>=256 <- producers cg 16..31)
            if (tid < 16) {
                poll_flag(&g_flag[bg][tid][0], tgt);
                __syncwarp(0x0000FFFFu);
                if (tid == 0) {
                    mbar_expect_tx(mbar0, 32768u);
                    bulk_g2s(h_smem, Hsrc, 32768u, mbar0);
                }
            } else if (tid < 32) {
                poll_flag(&g_flag[bg][tid][0], tgt);
                __syncwarp(0xFFFF0000u);
                if (tid == 16) {
                    mbar_expect_tx(mbar1, 32768u);
                    bulk_g2s(h_smem + 32768u, Hsrc + 8192, 32768u, mbar1);
                }
            }
            mbar_wait(my_mbar, ph);      // each half waits only its own data
        }

        // ---- GEMM: my k-half (256 k), R2 inner loop (FMA-bound @ 2 warps/SMSP) ----
        u64 a00 = 0, a01 = 0, a02 = 0, a03 = 0;
        u64 a10 = 0, a11 = 0, a12 = 0, a13 = 0;
        if (t > 0) {
            #pragma unroll 8
            for (int k = 0; k < 256; ++k) {
                ulonglong2 hA = *(const ulonglong2*)(hp + k * 32);      // b0..b3
                ulonglong2 hB = *(const ulonglong2*)(hp + k * 32 + 4);  // b4..b7
                float2 w = *(const float2*)(wp + k * 64);
                u64 W0 = pack2(w.x), W1 = pack2(w.y);
                ffma2(a00, hA.x, W0); ffma2(a01, hA.y, W0);
                ffma2(a02, hB.x, W0); ffma2(a03, hB.y, W0);
                ffma2(a10, hA.x, W1); ffma2(a11, hA.y, W1);
                ffma2(a12, hB.x, W1); ffma2(a13, hB.y, W1);
            }
        }

        // ---- scatter partial z: z2[kh][c][b] ----
        {
            float* zp = z2 + kh * 64 * ZPAD;
            int cc = 2 * lane;
            float* q0 = zp + cc * ZPAD + oct * 8;
            float* q1 = zp + (cc + 1) * ZPAD + oct * 8;
            *(u64*)(q0 + 0) = a00; *(u64*)(q0 + 2) = a01;
            *(u64*)(q0 + 4) = a02; *(u64*)(q0 + 6) = a03;
            *(u64*)(q1 + 0) = a10; *(u64*)(q1 + 2) = a11;
            *(u64*)(q1 + 4) = a12; *(u64*)(q1 + 6) = a13;
        }
        __syncthreads();

        // ---- gates: fold k-halves, 2 outputs per thread ----
        {
            float zlo[4], zhi[4];
            #pragma unroll
            for (int g = 0; g < 4; ++g) {
                int c = g * 16 + j;
                u64 v0 = *(const u64*)(z2 + c * ZPAD + b0);
                u64 v1 = *(const u64*)(z2 + 64 * ZPAD + c * ZPAD + b0);
                zlo[g] = lo32(v0) + lo32(v1);
                zhi[g] = hi32(v0) + hi32(v1);
            }
            float2 xv = *(const float2*)(x_s + b0);

            size_t obase = (size_t)(bg * 32 + b0) * TH
                         + (size_t)t * HID + cg * 16 + j;
            float h0r, h1r;
            #pragma unroll
            for (int r = 0; r < 2; ++r) {
                float xr = r ? xv.y : xv.x;
                float* zz = r ? zhi : zlo;
                float vi = zz[0] + xr * wi_r[0] + bi_r[0];
                float vf = zz[1] + xr * wi_r[1] + bi_r[1];
                float vg = zz[2] + xr * wi_r[2] + bi_r[2];
                float vo = zz[3] + xr * wi_r[3] + bi_r[3];
                float ig = 1.0f / (1.0f + __expf(-vi));
                float fg = 1.0f / (1.0f + __expf(-vf));
                float eg = __expf(2.0f * vg);
                float gv = 1.0f - 2.0f / (eg + 1.0f);          // tanh(vg)
                float og = 1.0f / (1.0f + __expf(-vo));
                float cp = r ? c1s : c0s;
                float cn = fg * cp + ig * gv;
                if (r) c1s = cn; else c0s = cn;
                float ec = __expf(2.0f * cn);
                float hr = og * (1.0f - 2.0f / (ec + 1.0f));   // o * tanh(c)
                if (r) h1r = hr; else h0r = hr;
                out[obase + (size_t)r * TH] = hr;
            }
            // k-major publish (STG.64: b0, b0+1 adjacent)
            float* hn = &g_Hbuf[(t + 1) & 1][bg][(cg * 16 + j) * 32 + b0];
            *(float2*)hn = make_float2(h0r, h1r);
        }

        // ---- release: all h published -> fence -> bump this CTA's flag ----
        __syncthreads();
        if (tid == 0) {
            __threadfence();
            asm volatile("st.release.gpu.global.u32 [%0], %1;"
                         :: "l"(&g_flag[bg][cg][0]), "r"((unsigned)(t + 1))
                         : "memory");
        }
    }
}

extern "C" void kernel_launch(void* const* d_in, const int* in_sizes, int n_in,
                              void* d_out, int out_size)
{
    // inputs: [0]=s (unused), [1]=x (128*2048), [2]=Wi (2048), [3]=Wh (512*2048), [4]=b (2048)
    const float* x    = (const float*)d_in[1];
    const float* Wi   = (const float*)d_in[2];
    const float* Wh   = (const float*)d_in[3];
    const float* bias = (const float*)d_in[4];
    float* out = (float*)d_out;

    size_t smem = (size_t)(53536 + 4) * sizeof(float);   // 214160 B
    cudaFuncSetAttribute(lstm_persistent_kernel,
                         cudaFuncAttributeMaxDynamicSharedMemorySize, (int)smem);

    lstm_init_kernel<<<1, 128>>>();
    lstm_persistent_kernel<<<128, 256, smem>>>(x, Wi, Wh, bias, out);
}

// round 9
// speedup vs baseline: 1.2350x; 1.0639x over previous
#include <cuda_runtime.h>
#include <cstdint>
#include <cstddef>

// Reverse LSTM: B=128, T=2048, H=512.  out[b,t,:] = h_t (consumes x[b, T-1-t]).
//
// Persistent kernel: 128 CTAs = 4 batch-groups (bg, 32 rows) x 32 col-groups
// (cg, 16 h-cols = 64 z-cols). Wh slice (128KB) SMEM-resident.
// R8: 512 threads/CTA = 4 warps per SMSP (R7's 2 were not enough to hide the
// LDS->FFMA2 dependency latency; fma-active time has been pipe-floor-constant
// ~7ms across all rounds while wall sat at 20-25ms). GEMM k-split 4 ways:
// warp w handles k-quarter w>>2 with the proven broadcast-h inner loop.
// Partial z folded 4-way via padded SMEM exchange. TMA staging in 2 halves.

#define TT   2048
#define HID  512
#define FPAD 32              // flag padding (uints) -> 128B per flag
#define ZPAD 34              // z exchange row pad (floats), even -> aligned u64

__device__ float    g_Hbuf[2][4][HID * 32];    // [parity][bg][k*32 + b]  k-major
__device__ unsigned g_flag[4][32][FPAD];       // [bg][cg][0], padded

typedef unsigned long long u64;

__device__ __forceinline__ void ffma2(u64 &d, u64 a, u64 b) {
    asm volatile("fma.rn.f32x2 %0, %1, %2, %0;" : "+l"(d) : "l"(a), "l"(b));
}
__device__ __forceinline__ u64 pack2(float x) {
    u64 r; asm("mov.b64 %0, {%1, %1};" : "=l"(r) : "f"(x)); return r;
}

__device__ __forceinline__ void poll_flag(const unsigned* f, unsigned tgt) {
    unsigned v;
    do {
        asm volatile("ld.acquire.gpu.global.u32 %0, [%1];" : "=r"(v) : "l"(f));
    } while (v < tgt);
}
__device__ __forceinline__ void bulk_g2s(unsigned dst_smem, const void* src,
                                         unsigned bytes, unsigned mbar) {
    asm volatile(
        "cp.async.bulk.shared::cluster.global.mbarrier::complete_tx::bytes "
        "[%0], [%1], %2, [%3];"
        :: "r"(dst_smem), "l"(src), "r"(bytes), "r"(mbar) : "memory");
}
__device__ __forceinline__ void mbar_init(unsigned mbar, unsigned cnt) {
    asm volatile("mbarrier.init.shared.b64 [%0], %1;" :: "r"(mbar), "r"(cnt) : "memory");
}
__device__ __forceinline__ void mbar_expect_tx(unsigned mbar, unsigned bytes) {
    asm volatile("mbarrier.arrive.expect_tx.shared.b64 _, [%0], %1;"
                 :: "r"(mbar), "r"(bytes) : "memory");
}
__device__ __forceinline__ void mbar_wait(unsigned mbar, unsigned parity) {
    unsigned done;
    asm volatile(
        "{\n\t.reg .pred p;\n\t"
        "mbarrier.try_wait.parity.acquire.cta.shared::cta.b64 p, [%1], %2;\n\t"
        "selp.b32 %0, 1, 0, p;\n\t}"
        : "=r"(done) : "r"(mbar), "r"(parity) : "memory");
    if (!done) {
        asm volatile(
            "{\n\t.reg .pred P1;\n\t"
            "WL_%=:\n\t"
            "mbarrier.try_wait.parity.acquire.cta.shared::cta.b64 P1, [%0], %1, 0x989680;\n\t"
            "@P1 bra.uni WD_%=;\n\t"
            "bra.uni WL_%=;\n\t"
            "WD_%=:\n\t}"
            :: "r"(mbar), "r"(parity) : "memory");
    }
}

__global__ void lstm_init_kernel() {
    int i = threadIdx.x;                // 128 = 4*32 flags
    g_flag[i >> 5][i & 31][0] = 0u;
}

extern __shared__ float sm[];

__global__ void __launch_bounds__(512, 1)
lstm_persistent_kernel(const float* __restrict__ x,
                       const float* __restrict__ Wi,
                       const float* __restrict__ Wh,
                       const float* __restrict__ bias,
                       float* __restrict__ out)
{
    // SMEM (floats):
    //  Wh_s [k=512][c=64]          @ 0       (131072 B)   c = g*16 + j
    //  h_s  [k=512][b=32]          @ 32768   ( 65536 B)   k-major
    //  z2   [q=4][c=64][ZPAD]      @ 49152   ( 34816 B)
    //  x_s  [32]                   @ 57856
    //  mbar u64 x2                 @ 57888   (16B aligned)
    float* Wh_s = sm;
    float* h_s  = sm + 32768;
    float* z2   = sm + 49152;
    float* x_s  = sm + 57856;

    const int tid = threadIdx.x;
    const int bg  = blockIdx.x >> 5;     // 0..3
    const int cg  = blockIdx.x & 31;     // 0..31 -> h-cols cg*16..cg*16+15

    const int wid  = tid >> 5;           // 0..15
    const int q    = wid >> 2;           // k-quarter 0..3 (k in [q*128,(q+1)*128))
    const int oct  = wid & 3;            // batch octet (b = oct*8 .. oct*8+7)
    const int lane = tid & 31;           // col-pair (cols 2*lane, 2*lane+1)

    const int j = tid & 15;              // gate-phase h-col
    const int b = tid >> 4;              // gate-phase batch row (0..31)

    const unsigned smem_base = (unsigned)__cvta_generic_to_shared(sm);
    const unsigned h_smem    = smem_base + 32768u * 4u;
    const unsigned mbar0     = smem_base + 57888u * 4u;
    const unsigned mbar1     = mbar0 + 8u;

    if (tid == 0) { mbar_init(mbar0, 1); mbar_init(mbar1, 1); }

    // ---- One-time: Wh slice (col c = g*16+j <-> global g*512 + cg*16 + j) ----
    for (int idx = tid; idx < HID * 64; idx += 512) {
        int k = idx >> 6, c = idx & 63;
        Wh_s[idx] = Wh[(size_t)k * 2048 + (c >> 4) * 512 + cg * 16 + (c & 15)];
    }
    float wi_r[4], bi_r[4];
    #pragma unroll
    for (int g = 0; g < 4; ++g) {
        wi_r[g] = Wi[g * 512 + cg * 16 + j];
        bi_r[g] = bias[g * 512 + cg * 16 + j];
    }
    __syncthreads();

    float cst = 0.f;                     // cell state for (b, j)
    const size_t TH = (size_t)TT * HID;

    const float* hp = h_s  + q * 4096 + oct * 8;
    const float* wp = Wh_s + q * 8192 + lane * 2;
    const unsigned my_mbar = (q < 2) ? mbar0 : mbar1;

    for (int t = 0; t < TT; ++t) {
        // x for this step (warp 1; consumed after the z2 syncthreads)
        if (tid >= 32 && tid < 64)
            x_s[tid - 32] = x[(size_t)(bg * 32 + (tid - 32)) * TT + (TT - 1 - t)];

        const unsigned ph = (unsigned)((t + 1) & 1);

        if (t > 0) {
            const float* Hsrc = &g_Hbuf[t & 1][bg][0];
            const unsigned tgt = (unsigned)t;
            // warp 0: lanes 0-15 gate half0 (k<256 <- producers cg 0..15),
            //         lanes 16-31 gate half1 (k>=256 <- producers cg 16..31)
            if (tid < 16) {
                poll_flag(&g_flag[bg][tid][0], tgt);
                __syncwarp(0x0000FFFFu);
                if (tid == 0) {
                    mbar_expect_tx(mbar0, 32768u);
                    bulk_g2s(h_smem, Hsrc, 32768u, mbar0);
                }
            } else if (tid < 32) {
                poll_flag(&g_flag[bg][tid][0], tgt);
                __syncwarp(0xFFFF0000u);
                if (tid == 16) {
                    mbar_expect_tx(mbar1, 32768u);
                    bulk_g2s(h_smem + 32768u, Hsrc + 8192, 32768u, mbar1);
                }
            }
            mbar_wait(my_mbar, ph);      // each half waits only its own data
        }

        // ---- GEMM: my k-quarter (128 k), broadcast-h inner loop ----
        u64 a00 = 0, a01 = 0, a02 = 0, a03 = 0;
        u64 a10 = 0, a11 = 0, a12 = 0, a13 = 0;
        if (t > 0) {
            #pragma unroll 8
            for (int k = 0; k < 128; ++k) {
                ulonglong2 hA = *(const ulonglong2*)(hp + k * 32);      // b0..b3
                ulonglong2 hB = *(const ulonglong2*)(hp + k * 32 + 4);  // b4..b7
                float2 w = *(const float2*)(wp + k * 64);
                u64 W0 = pack2(w.x), W1 = pack2(w.y);
                ffma2(a00, hA.x, W0); ffma2(a01, hA.y, W0);
                ffma2(a02, hB.x, W0); ffma2(a03, hB.y, W0);
                ffma2(a10, hA.x, W1); ffma2(a11, hA.y, W1);
                ffma2(a12, hB.x, W1); ffma2(a13, hB.y, W1);
            }
        }

        // ---- scatter partial z: z2[q][c][b] ----
        {
            float* zp = z2 + q * 64 * ZPAD;
            int cc = 2 * lane;
            float* p0 = zp + cc * ZPAD + oct * 8;
            float* p1 = zp + (cc + 1) * ZPAD + oct * 8;
            *(u64*)(p0 + 0) = a00; *(u64*)(p0 + 2) = a01;
            *(u64*)(p0 + 4) = a02; *(u64*)(p0 + 6) = a03;
            *(u64*)(p1 + 0) = a10; *(u64*)(p1 + 2) = a11;
            *(u64*)(p1 + 4) = a12; *(u64*)(p1 + 6) = a13;
        }
        __syncthreads();

        // ---- gates: fold 4 k-quarters, 1 output per thread ----
        {
            float zg_[4];
            #pragma unroll
            for (int g = 0; g < 4; ++g) {
                int c = g * 16 + j;
                zg_[g] = (z2[c * ZPAD + b]               + z2[64 * ZPAD + c * ZPAD + b])
                       + (z2[128 * ZPAD + c * ZPAD + b]  + z2[192 * ZPAD + c * ZPAD + b]);
            }
            float xr = x_s[b];
            float vi = zg_[0] + xr * wi_r[0] + bi_r[0];
            float vf = zg_[1] + xr * wi_r[1] + bi_r[1];
            float vg = zg_[2] + xr * wi_r[2] + bi_r[2];
            float vo = zg_[3] + xr * wi_r[3] + bi_r[3];
            float ig = 1.0f / (1.0f + __expf(-vi));
            float fg = 1.0f / (1.0f + __expf(-vf));
            float eg = __expf(2.0f * vg);
            float gv = 1.0f - 2.0f / (eg + 1.0f);          // tanh(vg)
            float og = 1.0f / (1.0f + __expf(-vo));
            float cn = fg * cst + ig * gv;
            cst = cn;
            float ec = __expf(2.0f * cn);
            float hr = og * (1.0f - 2.0f / (ec + 1.0f));   // o * tanh(c)

            out[(size_t)(bg * 32 + b) * TH + (size_t)t * HID + cg * 16 + j] = hr;
            // k-major publish for next step's bulk-staged GEMM loads
            g_Hbuf[(t + 1) & 1][bg][(cg * 16 + j) * 32 + b] = hr;
        }

        // ---- release: all h published -> fence -> bump this CTA's flag ----
        __syncthreads();
        if (tid == 0) {
            __threadfence();
            asm volatile("st.release.gpu.global.u32 [%0], %1;"
                         :: "l"(&g_flag[bg][cg][0]), "r"((unsigned)(t + 1))
                         : "memory");
        }
    }
}

extern "C" void kernel_launch(void* const* d_in, const int* in_sizes, int n_in,
                              void* d_out, int out_size)
{
    // inputs: [0]=s (unused), [1]=x (128*2048), [2]=Wi (2048), [3]=Wh (512*2048), [4]=b (2048)
    const float* x    = (const float*)d_in[1];
    const float* Wi   = (const float*)d_in[2];
    const float* Wh   = (const float*)d_in[3];
    const float* bias = (const float*)d_in[4];
    float* out = (float*)d_out;

    size_t smem = (size_t)(57888 + 4) * sizeof(float);   // 231568 B
    cudaFuncSetAttribute(lstm_persistent_kernel,
                         cudaFuncAttributeMaxDynamicSharedMemorySize, (int)smem);

    lstm_init_kernel<<<1, 128>>>();
    lstm_persistent_kernel<<<128, 512, smem>>>(x, Wi, Wh, bias, out);
}